// round 4
// baseline (speedup 1.0000x reference)
#include <cuda_runtime.h>
#include <math.h>

// Problem dims
#define BB 64
#define TT 2048
#define II 512
#define HH 512
#define GG 2048            // 4*H
#define NC 128             // persistent CTAs (<= 148 SMs -> co-resident)
#define TPB 256
#define HS_STRIDE 516      // 512 + 4 pad: stride in floats; 129 float4s (odd) -> conflict-free

// ---------------- device scratch (static: no allocation APIs allowed) ----------------
__device__ float    g_gatesx[(size_t)BB * TT * GG];   // 1 GB: gates_x[b][t][g]
__device__ float    g_hbuf[2][BB * HH];               // double-buffered hidden state
__device__ unsigned g_bar;                            // grid barrier counter

// ---------------- init: reset barrier + h0 (runs every launch) ----------------
__global__ void init_k() {
    int i = blockIdx.x * blockDim.x + threadIdx.x;
    if (i == 0) g_bar = 0u;
    for (int k = i; k < BB * HH; k += gridDim.x * blockDim.x) g_hbuf[0][k] = 0.f;
}

// ---------------- phase 1: gates_x = x @ Wx^T + bx + bh ----------------
// M = B*T = 131072 (row m = b*T + t, matches x layout), N = 2048, K = 512.
// 128x128 tile, BK=16, 256 threads, 8x8 per thread. FFMA-bound.
__global__ __launch_bounds__(256) void gemm_x_kernel(
    const float* __restrict__ x, const float* __restrict__ Wx,
    const float* __restrict__ bx, const float* __restrict__ bh)
{
    __shared__ float As[16][128];
    __shared__ float Bs[16][128];
    const int m0 = blockIdx.x * 128;
    const int n0 = blockIdx.y * 128;
    const int tid = threadIdx.x;
    const int tx = tid & 15, ty = tid >> 4;

    float acc[8][8];
#pragma unroll
    for (int i = 0; i < 8; i++)
#pragma unroll
        for (int j = 0; j < 8; j++) acc[i][j] = 0.f;

    for (int k0 = 0; k0 < II; k0 += 16) {
#pragma unroll
        for (int r = 0; r < 2; r++) {
            int v = tid + r * 256;          // 0..511
            int row = v >> 2, c4 = v & 3;   // 128 rows x 4 float4
            float4 a = *(const float4*)(x + (size_t)(m0 + row) * II + k0 + c4 * 4);
            As[c4 * 4 + 0][row] = a.x; As[c4 * 4 + 1][row] = a.y;
            As[c4 * 4 + 2][row] = a.z; As[c4 * 4 + 3][row] = a.w;
            float4 b = *(const float4*)(Wx + (size_t)(n0 + row) * II + k0 + c4 * 4);
            Bs[c4 * 4 + 0][row] = b.x; Bs[c4 * 4 + 1][row] = b.y;
            Bs[c4 * 4 + 2][row] = b.z; Bs[c4 * 4 + 3][row] = b.w;
        }
        __syncthreads();
#pragma unroll
        for (int kk = 0; kk < 16; kk++) {
            float4 a0 = *(const float4*)&As[kk][ty * 8];
            float4 a1 = *(const float4*)&As[kk][ty * 8 + 4];
            float4 b0 = *(const float4*)&Bs[kk][tx * 8];
            float4 b1 = *(const float4*)&Bs[kk][tx * 8 + 4];
            float a[8] = {a0.x, a0.y, a0.z, a0.w, a1.x, a1.y, a1.z, a1.w};
            float b[8] = {b0.x, b0.y, b0.z, b0.w, b1.x, b1.y, b1.z, b1.w};
#pragma unroll
            for (int i = 0; i < 8; i++)
#pragma unroll
                for (int j = 0; j < 8; j++) acc[i][j] += a[i] * b[j];
        }
        __syncthreads();
    }

    const int n = n0 + tx * 8;
    float bb[8];
#pragma unroll
    for (int j = 0; j < 8; j++) bb[j] = bx[n + j] + bh[n + j];
#pragma unroll
    for (int i = 0; i < 8; i++) {
        size_t m = (size_t)(m0 + ty * 8 + i);
        float* op = g_gatesx + m * GG + n;
        float4 v0 = make_float4(acc[i][0] + bb[0], acc[i][1] + bb[1],
                                acc[i][2] + bb[2], acc[i][3] + bb[3]);
        float4 v1 = make_float4(acc[i][4] + bb[4], acc[i][5] + bb[5],
                                acc[i][6] + bb[6], acc[i][7] + bb[7]);
        *(float4*)op = v0;
        *(float4*)(op + 4) = v1;
    }
}

// ---------------- phase 2: persistent recurrence ----------------
// 128 CTAs x 256 threads. CTA owns j in [j0, j0+4). Thread (b, jq) computes
// gates i,f,g,o for (b, j0+jq); c,h stay in registers across all 2048 steps.
// Wh slice (16 rows x 512) resident in SMEM; reads are warp-uniform broadcasts.
// h staged per step from global (L2) into padded SMEM. Double-buffered h +
// one fenced grid barrier per step.
extern __shared__ float smem[];
__global__ __launch_bounds__(256) void lstm_rec_kernel(
    const float* __restrict__ Wh, float* __restrict__ out)
{
    float* Whs = smem;                       // 16*512 floats
    float* hs  = smem + 16 * II;             // 64 rows, stride HS_STRIDE
    float* gxs = hs + BB * HS_STRIDE;        // 64*16 floats

    const int tid = threadIdx.x;
    const int j0  = blockIdx.x * 4;
    const int b   = tid & 63;
    const int jq  = tid >> 6;
    const int j   = j0 + jq;

    // Load Wh slice: row r = jq*4 + gate  <-  Wh[gate*H + j0 + jq][:]
    for (int idx = tid; idx < 16 * II; idx += TPB) {
        int r = idx >> 9, k = idx & 511;
        int gate = r & 3, q = r >> 2;
        Whs[idx] = Wh[(size_t)(gate * HH + j0 + q) * HH + k];
    }

    const float4* wi = (const float4*)(Whs + (jq * 4 + 0) * II);
    const float4* wf = (const float4*)(Whs + (jq * 4 + 1) * II);
    const float4* wg = (const float4*)(Whs + (jq * 4 + 2) * II);
    const float4* wo = (const float4*)(Whs + (jq * 4 + 3) * II);
    const float4* hrow = (const float4*)(hs + b * HS_STRIDE);

    const int sb = tid >> 2;    // staging: b index for gates_x tile
    const int sg = tid & 3;     // staging: gate index

    float c = 0.f, h = 0.f;
    unsigned target = NC;

    for (int t = 0; t < TT; t++) {
        // ---- stage h (read buffer t&1; bypass L1 — other SMs wrote it) ----
        const float4* gh4 = (const float4*)g_hbuf[t & 1];
        for (int idx = tid; idx < (BB * II) / 4; idx += TPB) {
            int b_ = idx >> 7, k4 = idx & 127;
            float4 v = __ldcg(gh4 + idx);
            *(float4*)(hs + b_ * HS_STRIDE + k4 * 4) = v;
        }
        // ---- stage gates_x[b][t][gate*512 + j0 .. +3] (one float4/thread) ----
        {
            float4 v = *(const float4*)(g_gatesx +
                          ((size_t)sb * TT + t) * GG + (size_t)sg * HH + j0);
            ((float4*)gxs)[tid] = v;
        }
        __syncthreads();

        // ---- 4 dot products of length 512 (FFMA-bound core) ----
        float ai = 0.f, af = 0.f, ag = 0.f, ao = 0.f;
#pragma unroll 4
        for (int k4 = 0; k4 < 128; k4++) {
            float4 hv = hrow[k4];
            float4 a = wi[k4];  ai += hv.x * a.x + hv.y * a.y + hv.z * a.z + hv.w * a.w;
            float4 f4 = wf[k4]; af += hv.x * f4.x + hv.y * f4.y + hv.z * f4.z + hv.w * f4.w;
            float4 g4 = wg[k4]; ag += hv.x * g4.x + hv.y * g4.y + hv.z * g4.z + hv.w * g4.w;
            float4 o4 = wo[k4]; ao += hv.x * o4.x + hv.y * o4.y + hv.z * o4.z + hv.w * o4.w;
        }

        // ---- pointwise LSTM cell ----
        float xi = ai + gxs[b * 16 + 0  + jq];
        float xf = af + gxs[b * 16 + 4  + jq];
        float xg = ag + gxs[b * 16 + 8  + jq];
        float xo = ao + gxs[b * 16 + 12 + jq];
        float si = 1.f / (1.f + expf(-xi));
        float sf = 1.f / (1.f + expf(-xf));
        float tg = tanhf(xg);
        float so = 1.f / (1.f + expf(-xo));
        c = sf * c + si * tg;
        h = so * tanhf(c);

        out[((size_t)b * TT + t) * HH + j] = h;
        g_hbuf[(t & 1) ^ 1][b * HH + j] = h;   // write the other buffer

        // ---- grid barrier (release h writes, acquire for next staging) ----
        __threadfence();
        __syncthreads();
        if (tid == 0) {
            atomicAdd(&g_bar, 1u);
            while (*(volatile unsigned*)&g_bar < target) { }
            __threadfence();
        }
        __syncthreads();
        target += NC;
    }

    // finals: h_n then c_n appended after output
    out[(size_t)BB * TT * HH + (size_t)b * HH + j] = h;
    out[(size_t)BB * TT * HH + BB * HH + (size_t)b * HH + j] = c;
}

// ---------------- launch ----------------
extern "C" void kernel_launch(void* const* d_in, const int* in_sizes, int n_in,
                              void* d_out, int out_size)
{
    const float* x  = (const float*)d_in[0];
    const float* Wx = (const float*)d_in[1];
    const float* bx = (const float*)d_in[2];
    const float* Wh = (const float*)d_in[3];
    const float* bh = (const float*)d_in[4];
    float* out = (float*)d_out;

    init_k<<<32, 256>>>();

    dim3 grid_g(131072 / 128, GG / 128);   // 1024 x 16
    gemm_x_kernel<<<grid_g, 256>>>(x, Wx, bx, bh);

    const int smem_bytes = (16 * II + BB * HS_STRIDE + BB * 16) * (int)sizeof(float); // 168960
    cudaFuncSetAttribute(lstm_rec_kernel,
                         cudaFuncAttributeMaxDynamicSharedMemorySize, smem_bytes);
    lstm_rec_kernel<<<NC, TPB, smem_bytes>>>(Wh, out);
    (void)in_sizes; (void)n_in; (void)out_size;
}

// round 6
// speedup vs baseline: 1.2187x; 1.2187x over previous
#include <cuda_runtime.h>
#include <cuda_bf16.h>
#include <math.h>
#include <stdint.h>

#define BB 64
#define TT 2048
#define II 512
#define HH 512
#define GG 2048
#define NC 128
#define TPB 256
#define HS_STRIDE 516

__device__ float         g_gatesx[(size_t)BB * TT * GG];
__device__ __nv_bfloat16 g_xh[(size_t)BB * TT * II];
__device__ __nv_bfloat16 g_xl[(size_t)BB * TT * II];
__device__ __nv_bfloat16 g_wxh[(size_t)GG * II];
__device__ __nv_bfloat16 g_wxl[(size_t)GG * II];
__device__ float         g_hbuf[2][BB * HH];
__device__ unsigned      g_bar;

__device__ __forceinline__ uint32_t smem_u32(const void* p) {
    return (uint32_t)__cvta_generic_to_shared(p);
}
#define SWZ(o) ((o) ^ (((o) >> 3) & 0x70))

// ---- baseline-ISA building blocks (sm_80+; safe on plain sm_103 target) ----
__device__ __forceinline__ void ldsm4(uint32_t* r, uint32_t a) {
    asm volatile("ldmatrix.sync.aligned.m8n8.x4.shared.b16 {%0,%1,%2,%3}, [%4];"
                 : "=r"(r[0]), "=r"(r[1]), "=r"(r[2]), "=r"(r[3]) : "r"(a));
}
__device__ __forceinline__ void mma16816(float* c, const uint32_t* a,
                                         uint32_t b0, uint32_t b1) {
    asm volatile(
        "mma.sync.aligned.m16n8k16.row.col.f32.bf16.bf16.f32 "
        "{%0,%1,%2,%3},{%4,%5,%6,%7},{%8,%9},{%0,%1,%2,%3};"
        : "+f"(c[0]), "+f"(c[1]), "+f"(c[2]), "+f"(c[3])
        : "r"(a[0]), "r"(a[1]), "r"(a[2]), "r"(a[3]), "r"(b0), "r"(b1));
}
__device__ __forceinline__ void cpasync16(uint32_t s, const void* g) {
    asm volatile("cp.async.cg.shared.global [%0], [%1], 16;" :: "r"(s), "l"(g));
}
#define CP_COMMIT() asm volatile("cp.async.commit_group;" ::: "memory")
#define CP_WAIT0()  asm volatile("cp.async.wait_group 0;" ::: "memory")

// packed fp32x2 (FFMA2) — sm_100-family base feature, no 'a' suffix needed
__device__ __forceinline__ void lds_v2(uint64_t& a, uint64_t& b, uint32_t addr) {
    asm volatile("ld.shared.v2.b64 {%0,%1}, [%2];" : "=l"(a), "=l"(b) : "r"(addr));
}
__device__ __forceinline__ void ffma2(uint64_t& d, uint64_t a, uint64_t b) {
    asm("fma.rn.f32x2 %0, %1, %2, %0;" : "+l"(d) : "l"(a), "l"(b));
}
__device__ __forceinline__ float2 unpk(uint64_t v) {
    float2 r; asm("mov.b64 {%0,%1}, %2;" : "=f"(r.x), "=f"(r.y) : "l"(v)); return r;
}

__global__ void init_k() {
    int i = blockIdx.x * blockDim.x + threadIdx.x;
    if (i == 0) g_bar = 0u;
    for (int k = i; k < BB * HH; k += gridDim.x * blockDim.x) g_hbuf[0][k] = 0.f;
}

// ---- fp32 -> bf16 hi/lo split ----
__device__ __forceinline__ void split4(float4 v, __nv_bfloat16* hi, __nv_bfloat16* lo,
                                       size_t i) {
    __nv_bfloat16 hx = __float2bfloat16(v.x), hy = __float2bfloat16(v.y);
    __nv_bfloat16 hz = __float2bfloat16(v.z), hw = __float2bfloat16(v.w);
    ((__nv_bfloat162*)hi)[2 * i]     = __halves2bfloat162(hx, hy);
    ((__nv_bfloat162*)hi)[2 * i + 1] = __halves2bfloat162(hz, hw);
    ((__nv_bfloat162*)lo)[2 * i] = __halves2bfloat162(
        __float2bfloat16(v.x - __bfloat162float(hx)),
        __float2bfloat16(v.y - __bfloat162float(hy)));
    ((__nv_bfloat162*)lo)[2 * i + 1] = __halves2bfloat162(
        __float2bfloat16(v.z - __bfloat162float(hz)),
        __float2bfloat16(v.w - __bfloat162float(hw)));
}
__global__ void cvt_x_kernel(const float* __restrict__ src) {
    size_t n4 = (size_t)BB * TT * II / 4, st = (size_t)gridDim.x * blockDim.x;
    for (size_t i = blockIdx.x * (size_t)blockDim.x + threadIdx.x; i < n4; i += st)
        split4(((const float4*)src)[i], g_xh, g_xl, i);
}
__global__ void cvt_w_kernel(const float* __restrict__ src) {
    size_t n4 = (size_t)GG * II / 4, st = (size_t)gridDim.x * blockDim.x;
    for (size_t i = blockIdx.x * (size_t)blockDim.x + threadIdx.x; i < n4; i += st)
        split4(((const float4*)src)[i], g_wxh, g_wxl, i);
}

// ---- phase 1: mma.sync split-bf16 GEMM ----
// C[m][n] = sum_k x[m][k] Wx[n][k] + (bx+bh)[n],  M=131072  N=2048  K=512.
// CTA tile 128x128, K staged in 64-col chunks (Ah/Al/Bh/Bl, 16KB each, SW128),
// double-buffered via cp.async. Warp grid 4(m) x 2(n); warp tile 32x64.
#define STAGE_BYTES 65536
#define GSMEM_TOTAL (1024 + 2 * STAGE_BYTES)

__global__ __launch_bounds__(256) void gemm_x_mma(
    const float* __restrict__ bx, const float* __restrict__ bh)
{
    extern __shared__ char smem[];
    float* bias_s = (float*)smem;                    // 512 B
    char*  tiles  = smem + 1024;
    const uint32_t tb = smem_u32(tiles);
    const int tid = threadIdx.x, lane = tid & 31, w = tid >> 5;
    const int wm = w & 3, wn = w >> 2;               // warp coords
    const int n0 = blockIdx.x * 128;
    const size_t m0 = (size_t)blockIdx.y * 128;

    if (tid < 128) bias_s[tid] = bx[n0 + tid] + bh[n0 + tid];

    auto stage = [&](int c, int buf) {
        uint32_t base = tb + buf * STAGE_BYTES;
#pragma unroll
        for (int i = 0; i < 16; i++) {
            int idx = tid + i * 256;                 // 0..4095
            int t = idx >> 10, r = (idx >> 3) & 127, ck = idx & 7;
            const __nv_bfloat16* src;
            if (t == 0)      src = g_xh  + (m0 + r) * II;
            else if (t == 1) src = g_xl  + (m0 + r) * II;
            else if (t == 2) src = g_wxh + (size_t)(n0 + r) * II;
            else             src = g_wxl + (size_t)(n0 + r) * II;
            cpasync16(base + t * 16384 + SWZ(r * 128 + ck * 16),
                      (const char*)src + c * 128 + ck * 16);
        }
        CP_COMMIT();
    };

    float acc[2][8][4];
#pragma unroll
    for (int a = 0; a < 2; a++)
#pragma unroll
        for (int bq = 0; bq < 8; bq++)
#pragma unroll
            for (int q = 0; q < 4; q++) acc[a][bq][q] = 0.f;

    stage(0, 0);
    for (int c = 0; c < 8; c++) {
        CP_WAIT0();
        __syncthreads();
        if (c < 7) stage(c + 1, (c + 1) & 1);

        const uint32_t bA = tb + (c & 1) * STAGE_BYTES;
#pragma unroll
        for (int kk = 0; kk < 4; kk++) {
            const int kb = kk * 32;
            uint32_t ah[2][4], al[2][4];
#pragma unroll
            for (int mt = 0; mt < 2; mt++) {
                int arow = wm * 32 + mt * 16 + (lane & 15);
                uint32_t aoff = SWZ(arow * 128 + kb + (lane >> 4) * 16);
                ldsm4(ah[mt], bA + aoff);              // Ah tile
                ldsm4(al[mt], bA + 16384 + aoff);      // Al tile
            }
#pragma unroll
            for (int ng = 0; ng < 4; ng++) {
                int brow = wn * 64 + ng * 16 + ((lane >> 4) & 1) * 8 + (lane & 7);
                uint32_t boff = SWZ(brow * 128 + kb + ((lane >> 3) & 1) * 16);
                uint32_t bhf[4], blf[4];
                ldsm4(bhf, bA + 32768 + boff);         // Bh
                ldsm4(blf, bA + 49152 + boff);         // Bl
#pragma unroll
                for (int mt = 0; mt < 2; mt++) {
                    mma16816(acc[mt][ng * 2],     ah[mt], bhf[0], bhf[1]);
                    mma16816(acc[mt][ng * 2],     ah[mt], blf[0], blf[1]);
                    mma16816(acc[mt][ng * 2],     al[mt], bhf[0], bhf[1]);
                    mma16816(acc[mt][ng * 2 + 1], ah[mt], bhf[2], bhf[3]);
                    mma16816(acc[mt][ng * 2 + 1], ah[mt], blf[2], blf[3]);
                    mma16816(acc[mt][ng * 2 + 1], al[mt], bhf[2], bhf[3]);
                }
            }
        }
        __syncthreads();
    }

    // epilogue: +bias, float2 stores (4 lanes -> one 32B sector)
#pragma unroll
    for (int mt = 0; mt < 2; mt++) {
        size_t row = m0 + wm * 32 + mt * 16 + (lane >> 2);
#pragma unroll
        for (int nf = 0; nf < 8; nf++) {
            int cl = wn * 64 + nf * 8 + (lane & 3) * 2;
            float b0 = bias_s[cl], b1 = bias_s[cl + 1];
            float* p0 = g_gatesx + row * GG + n0 + cl;
            float* p1 = g_gatesx + (row + 8) * GG + n0 + cl;
            *(float2*)p0 = make_float2(acc[mt][nf][0] + b0, acc[mt][nf][1] + b1);
            *(float2*)p1 = make_float2(acc[mt][nf][2] + b0, acc[mt][nf][3] + b1);
        }
    }
}

// ---- phase 2: persistent recurrence, FFMA2 core ----
__global__ __launch_bounds__(256) void lstm_rec_kernel(
    const float* __restrict__ Wh, float* __restrict__ out)
{
    extern __shared__ float rsmem[];
    float* Whs = rsmem;
    float* hs  = rsmem + 16 * II;
    float* gxs = hs + BB * HS_STRIDE;

    const int tid = threadIdx.x;
    const int j0  = blockIdx.x * 4;
    const int b   = tid & 63;
    const int jq  = tid >> 6;
    const int j   = j0 + jq;

    for (int idx = tid; idx < 16 * II; idx += TPB) {
        int r = idx >> 9, k = idx & 511;
        int gate = r & 3, q = r >> 2;
        Whs[idx] = Wh[(size_t)(gate * HH + j0 + q) * HH + k];
    }

    const uint32_t hsa = smem_u32(hs + b * HS_STRIDE);
    const uint32_t wa0 = smem_u32(Whs + (jq * 4) * II);
    const uint32_t wa1 = wa0 + II * 4, wa2 = wa0 + 2 * II * 4, wa3 = wa0 + 3 * II * 4;
    const int sb = tid >> 2, sg = tid & 3;

    float c = 0.f, h = 0.f;
    unsigned target = NC;

    for (int t = 0; t < TT; t++) {
        float4 gxv = *(const float4*)(g_gatesx +
                        ((size_t)sb * TT + t) * GG + (size_t)sg * HH + j0);
        const float4* gh4 = (const float4*)g_hbuf[t & 1];
#pragma unroll 4
        for (int idx = tid; idx < (BB * II) / 4; idx += TPB) {
            int b_ = idx >> 7, k4 = idx & 127;
            float4 v = __ldcg(gh4 + idx);
            *(float4*)(hs + b_ * HS_STRIDE + k4 * 4) = v;
        }
        ((float4*)gxs)[tid] = gxv;
        __syncthreads();

        uint64_t a0 = 0, a1 = 0, a2 = 0, a3 = 0, a4 = 0, a5 = 0, a6 = 0, a7 = 0;
#pragma unroll 4
        for (int k4 = 0; k4 < 128; k4++) {
            uint32_t o = (uint32_t)k4 * 16;
            uint64_t h0, h1, w0, w1;
            lds_v2(h0, h1, hsa + o);
            lds_v2(w0, w1, wa0 + o); ffma2(a0, h0, w0); ffma2(a1, h1, w1);
            lds_v2(w0, w1, wa1 + o); ffma2(a2, h0, w0); ffma2(a3, h1, w1);
            lds_v2(w0, w1, wa2 + o); ffma2(a4, h0, w0); ffma2(a5, h1, w1);
            lds_v2(w0, w1, wa3 + o); ffma2(a6, h0, w0); ffma2(a7, h1, w1);
        }
        float2 p0 = unpk(a0), p1 = unpk(a1), p2 = unpk(a2), p3 = unpk(a3);
        float2 p4 = unpk(a4), p5 = unpk(a5), p6 = unpk(a6), p7 = unpk(a7);

        float xi = p0.x + p0.y + p1.x + p1.y + gxs[b * 16 + 0  + jq];
        float xf = p2.x + p2.y + p3.x + p3.y + gxs[b * 16 + 4  + jq];
        float xg = p4.x + p4.y + p5.x + p5.y + gxs[b * 16 + 8  + jq];
        float xo = p6.x + p6.y + p7.x + p7.y + gxs[b * 16 + 12 + jq];
        float si = 1.f / (1.f + expf(-xi));
        float sf = 1.f / (1.f + expf(-xf));
        float tg = tanhf(xg);
        float so = 1.f / (1.f + expf(-xo));
        c = sf * c + si * tg;
        h = so * tanhf(c);

        out[((size_t)b * TT + t) * HH + j] = h;
        g_hbuf[(t & 1) ^ 1][b * HH + j] = h;

        __threadfence();
        __syncthreads();
        if (tid == 0) {
            atomicAdd(&g_bar, 1u);
            while (*(volatile unsigned*)&g_bar < target) { }
            __threadfence();
        }
        __syncthreads();
        target += NC;
    }

    out[(size_t)BB * TT * HH + (size_t)b * HH + j] = h;
    out[(size_t)BB * TT * HH + BB * HH + (size_t)b * HH + j] = c;
}

extern "C" void kernel_launch(void* const* d_in, const int* in_sizes, int n_in,
                              void* d_out, int out_size)
{
    const float* x  = (const float*)d_in[0];
    const float* Wx = (const float*)d_in[1];
    const float* bx = (const float*)d_in[2];
    const float* Wh = (const float*)d_in[3];
    const float* bh = (const float*)d_in[4];
    float* out = (float*)d_out;

    init_k<<<32, 256>>>();
    cvt_x_kernel<<<2048, 256>>>(x);
    cvt_w_kernel<<<64, 256>>>(Wx);

    cudaFuncSetAttribute(gemm_x_mma,
                         cudaFuncAttributeMaxDynamicSharedMemorySize, GSMEM_TOTAL);
    dim3 grid_g(GG / 128, 131072 / 128);   // 16 x 1024, N fastest
    gemm_x_mma<<<grid_g, 256, GSMEM_TOTAL>>>(bx, bh);

    const int rs_bytes = (16 * II + BB * HS_STRIDE + BB * 16) * (int)sizeof(float);
    cudaFuncSetAttribute(lstm_rec_kernel,
                         cudaFuncAttributeMaxDynamicSharedMemorySize, rs_bytes);
    lstm_rec_kernel<<<NC, TPB, rs_bytes>>>(Wh, out);
    (void)in_sizes; (void)n_in; (void)out_size;
}

// round 7
// speedup vs baseline: 2.2439x; 1.8412x over previous
#include <cuda_runtime.h>
#include <cuda_bf16.h>
#include <math.h>
#include <stdint.h>

#define BB 64
#define TT 2048
#define II 512
#define HH 512
#define GG 2048
#define NC 128
#define TPB 256

__device__ float         g_gatesx[(size_t)BB * TT * GG];
__device__ __nv_bfloat16 g_xh[(size_t)BB * TT * II];
__device__ __nv_bfloat16 g_xl[(size_t)BB * TT * II];
__device__ __nv_bfloat16 g_wxh[(size_t)GG * II];
__device__ __nv_bfloat16 g_wxl[(size_t)GG * II];
__device__ __nv_bfloat16 g_whh[(size_t)GG * HH];   // Wh hi
__device__ __nv_bfloat16 g_whl[(size_t)GG * HH];   // Wh lo
__device__ __nv_bfloat16 g_hh[2][BB * HH];         // h hi, ping-pong
__device__ __nv_bfloat16 g_hl[2][BB * HH];         // h lo
__device__ unsigned      g_bar;

__device__ __forceinline__ uint32_t smem_u32(const void* p) {
    return (uint32_t)__cvta_generic_to_shared(p);
}
#define SWZ(o) ((o) ^ (((o) >> 3) & 0x70))

__device__ __forceinline__ void ldsm4(uint32_t* r, uint32_t a) {
    asm volatile("ldmatrix.sync.aligned.m8n8.x4.shared.b16 {%0,%1,%2,%3}, [%4];"
                 : "=r"(r[0]), "=r"(r[1]), "=r"(r[2]), "=r"(r[3]) : "r"(a));
}
__device__ __forceinline__ void mma16816(float* c, const uint32_t* a,
                                         uint32_t b0, uint32_t b1) {
    asm volatile(
        "mma.sync.aligned.m16n8k16.row.col.f32.bf16.bf16.f32 "
        "{%0,%1,%2,%3},{%4,%5,%6,%7},{%8,%9},{%0,%1,%2,%3};"
        : "+f"(c[0]), "+f"(c[1]), "+f"(c[2]), "+f"(c[3])
        : "r"(a[0]), "r"(a[1]), "r"(a[2]), "r"(a[3]), "r"(b0), "r"(b1));
}
__device__ __forceinline__ void cpasync16(uint32_t s, const void* g) {
    asm volatile("cp.async.cg.shared.global [%0], [%1], 16;" :: "r"(s), "l"(g));
}
#define CP_COMMIT() asm volatile("cp.async.commit_group;" ::: "memory")
#define CP_WAIT0()  asm volatile("cp.async.wait_group 0;" ::: "memory")

__global__ void init_k() {
    int i = blockIdx.x * blockDim.x + threadIdx.x;
    if (i == 0) g_bar = 0u;
    for (int k = i; k < BB * HH; k += gridDim.x * blockDim.x) {
        g_hh[0][k] = __float2bfloat16(0.f);
        g_hl[0][k] = __float2bfloat16(0.f);
    }
}

// ---- fp32 -> bf16 hi/lo split ----
__device__ __forceinline__ void split4(float4 v, __nv_bfloat16* hi, __nv_bfloat16* lo,
                                       size_t i) {
    __nv_bfloat16 hx = __float2bfloat16(v.x), hy = __float2bfloat16(v.y);
    __nv_bfloat16 hz = __float2bfloat16(v.z), hw = __float2bfloat16(v.w);
    ((__nv_bfloat162*)hi)[2 * i]     = __halves2bfloat162(hx, hy);
    ((__nv_bfloat162*)hi)[2 * i + 1] = __halves2bfloat162(hz, hw);
    ((__nv_bfloat162*)lo)[2 * i] = __halves2bfloat162(
        __float2bfloat16(v.x - __bfloat162float(hx)),
        __float2bfloat16(v.y - __bfloat162float(hy)));
    ((__nv_bfloat162*)lo)[2 * i + 1] = __halves2bfloat162(
        __float2bfloat16(v.z - __bfloat162float(hz)),
        __float2bfloat16(v.w - __bfloat162float(hw)));
}
__global__ void cvt_x_kernel(const float* __restrict__ src) {
    size_t n4 = (size_t)BB * TT * II / 4, st = (size_t)gridDim.x * blockDim.x;
    for (size_t i = blockIdx.x * (size_t)blockDim.x + threadIdx.x; i < n4; i += st)
        split4(((const float4*)src)[i], g_xh, g_xl, i);
}
__global__ void cvt_w_kernel(const float* __restrict__ src) {
    size_t n4 = (size_t)GG * II / 4, st = (size_t)gridDim.x * blockDim.x;
    for (size_t i = blockIdx.x * (size_t)blockDim.x + threadIdx.x; i < n4; i += st)
        split4(((const float4*)src)[i], g_wxh, g_wxl, i);
}
__global__ void cvt_wh_kernel(const float* __restrict__ src) {
    size_t n4 = (size_t)GG * HH / 4, st = (size_t)gridDim.x * blockDim.x;
    for (size_t i = blockIdx.x * (size_t)blockDim.x + threadIdx.x; i < n4; i += st)
        split4(((const float4*)src)[i], g_whh, g_whl, i);
}

// ---- phase 1: mma.sync split-bf16 GEMM (unchanged from R6) ----
#define STAGE_BYTES 65536
#define GSMEM_TOTAL (1024 + 2 * STAGE_BYTES)

__global__ __launch_bounds__(256) void gemm_x_mma(
    const float* __restrict__ bx, const float* __restrict__ bh)
{
    extern __shared__ char smem[];
    float* bias_s = (float*)smem;
    char*  tiles  = smem + 1024;
    const uint32_t tb = smem_u32(tiles);
    const int tid = threadIdx.x, lane = tid & 31, w = tid >> 5;
    const int wm = w & 3, wn = w >> 2;
    const int n0 = blockIdx.x * 128;
    const size_t m0 = (size_t)blockIdx.y * 128;

    if (tid < 128) bias_s[tid] = bx[n0 + tid] + bh[n0 + tid];

    auto stage = [&](int c, int buf) {
        uint32_t base = tb + buf * STAGE_BYTES;
#pragma unroll
        for (int i = 0; i < 16; i++) {
            int idx = tid + i * 256;
            int t = idx >> 10, r = (idx >> 3) & 127, ck = idx & 7;
            const __nv_bfloat16* src;
            if (t == 0)      src = g_xh  + (m0 + r) * II;
            else if (t == 1) src = g_xl  + (m0 + r) * II;
            else if (t == 2) src = g_wxh + (size_t)(n0 + r) * II;
            else             src = g_wxl + (size_t)(n0 + r) * II;
            cpasync16(base + t * 16384 + SWZ(r * 128 + ck * 16),
                      (const char*)src + c * 128 + ck * 16);
        }
        CP_COMMIT();
    };

    float acc[2][8][4];
#pragma unroll
    for (int a = 0; a < 2; a++)
#pragma unroll
        for (int bq = 0; bq < 8; bq++)
#pragma unroll
            for (int q = 0; q < 4; q++) acc[a][bq][q] = 0.f;

    stage(0, 0);
    for (int c = 0; c < 8; c++) {
        CP_WAIT0();
        __syncthreads();
        if (c < 7) stage(c + 1, (c + 1) & 1);

        const uint32_t bA = tb + (c & 1) * STAGE_BYTES;
#pragma unroll
        for (int kk = 0; kk < 4; kk++) {
            const int kb = kk * 32;
            uint32_t ah[2][4], al[2][4];
#pragma unroll
            for (int mt = 0; mt < 2; mt++) {
                int arow = wm * 32 + mt * 16 + (lane & 15);
                uint32_t aoff = SWZ(arow * 128 + kb + (lane >> 4) * 16);
                ldsm4(ah[mt], bA + aoff);
                ldsm4(al[mt], bA + 16384 + aoff);
            }
#pragma unroll
            for (int ng = 0; ng < 4; ng++) {
                int brow = wn * 64 + ng * 16 + ((lane >> 4) & 1) * 8 + (lane & 7);
                uint32_t boff = SWZ(brow * 128 + kb + ((lane >> 3) & 1) * 16);
                uint32_t bhf[4], blf[4];
                ldsm4(bhf, bA + 32768 + boff);
                ldsm4(blf, bA + 49152 + boff);
#pragma unroll
                for (int mt = 0; mt < 2; mt++) {
                    mma16816(acc[mt][ng * 2],     ah[mt], bhf[0], bhf[1]);
                    mma16816(acc[mt][ng * 2],     ah[mt], blf[0], blf[1]);
                    mma16816(acc[mt][ng * 2],     al[mt], bhf[0], bhf[1]);
                    mma16816(acc[mt][ng * 2 + 1], ah[mt], bhf[2], bhf[3]);
                    mma16816(acc[mt][ng * 2 + 1], ah[mt], blf[2], blf[3]);
                    mma16816(acc[mt][ng * 2 + 1], al[mt], bhf[2], bhf[3]);
                }
            }
        }
        __syncthreads();
    }

#pragma unroll
    for (int mt = 0; mt < 2; mt++) {
        size_t row = m0 + wm * 32 + mt * 16 + (lane >> 2);
#pragma unroll
        for (int nf = 0; nf < 8; nf++) {
            int cl = wn * 64 + nf * 8 + (lane & 3) * 2;
            float b0 = bias_s[cl], b1 = bias_s[cl + 1];
            float* p0 = g_gatesx + row * GG + n0 + cl;
            float* p1 = g_gatesx + (row + 8) * GG + n0 + cl;
            *(float2*)p0 = make_float2(acc[mt][nf][0] + b0, acc[mt][nf][1] + b1);
            *(float2*)p1 = make_float2(acc[mt][nf][2] + b0, acc[mt][nf][3] + b1);
        }
    }
}

// ---- phase 2: persistent recurrence, mma.sync core, weights in registers ----
// CTA = 4 j columns (16 gate rows, n = jq*4+gate). Per step:
//   G[64b x 16n] = h[64x512] @ WhT, split-bf16 (Ah·Bh + Ah·Bl + Al·Bh).
// K split over 8 warps (64 k each); Wh B-frags (hi+lo, 32 regs) loaded once.
// h staged per step as bf16 hi/lo into padded smem (1040B rows) for ldmatrix.
#define SM_HH 0                 // h hi: 64 rows x 1040B = 66560
#define SM_HL 66560             // h lo: 66560
#define SM_P  133120            // partials: 8 w x 64 b x 24 fl = 49152
#define SM_GX 182272            // gates_x tile: 4096
#define RSMEM_TOTAL 186368

__global__ __launch_bounds__(256) void lstm_rec_kernel(float* __restrict__ out)
{
    extern __shared__ char smp[];
    const uint32_t sbase = smem_u32(smp);
    const int tid = threadIdx.x, lane = tid & 31, w = tid >> 5;
    const int j0 = blockIdx.x * 4;
    const int b  = tid & 63;
    const int jq = tid >> 6;
    const int j  = j0 + jq;
    float* gxs = (float*)(smp + SM_GX);

    // ---- stage Wh slice (16 x 512, hi+lo) into P region, padded rows ----
#pragma unroll
    for (int i = 0; i < 4; i++) {
        int idx = tid + i * 256;               // 0..1023 (uint4 units)
        int n = idx >> 6, cc = idx & 63;
        int gate = n & 3, q = n >> 2;
        size_t grow = (size_t)(gate * HH + j0 + q) * HH;
        *(uint4*)(smp + SM_P + n * 1040 + cc * 16) =
            *((const uint4*)(g_whh + grow) + cc);
        *(uint4*)(smp + SM_P + 16640 + n * 1040 + cc * 16) =
            *((const uint4*)(g_whl + grow) + cc);
    }
    __syncthreads();

    // ---- load B-frags once: warp w owns k in [w*64, w*64+64) ----
    uint32_t Bh[2][4][2], Bl[2][4][2];
    {
        int brow = ((lane >> 4) & 1) * 8 + (lane & 7);
        uint32_t cb = w * 128 + ((lane >> 3) & 1) * 16;
#pragma unroll
        for (int kt = 0; kt < 4; kt++) {
            uint32_t off = brow * 1040 + cb + kt * 32;
            uint32_t r[4];
            ldsm4(r, sbase + SM_P + off);
            Bh[0][kt][0] = r[0]; Bh[0][kt][1] = r[1];
            Bh[1][kt][0] = r[2]; Bh[1][kt][1] = r[3];
            ldsm4(r, sbase + SM_P + 16640 + off);
            Bl[0][kt][0] = r[0]; Bl[0][kt][1] = r[1];
            Bl[1][kt][0] = r[2]; Bl[1][kt][1] = r[3];
        }
    }
    __syncthreads();   // P region free for partials now

    const int sb = tid >> 2, sg = tid & 3;
    float c = 0.f, h = 0.f;
    unsigned target = NC;

    for (int t = 0; t < TT; t++) {
        // prefetch gates_x (independent of h)
        float4 gxv = *(const float4*)(g_gatesx +
                        ((size_t)sb * TT + t) * GG + (size_t)sg * HH + j0);

        // ---- stage h hi/lo (bf16) into padded smem ----
        const uint4* srch = (const uint4*)g_hh[t & 1];
        const uint4* srcl = (const uint4*)g_hl[t & 1];
#pragma unroll
        for (int i = 0; i < 16; i++) {
            int idx = tid + i * 256;           // 0..4095 uint4
            int row = idx >> 6, cc = idx & 63;
            *(uint4*)(smp + SM_HH + row * 1040 + cc * 16) = __ldcg(srch + idx);
            *(uint4*)(smp + SM_HL + row * 1040 + cc * 16) = __ldcg(srcl + idx);
        }
        ((float4*)gxs)[tid] = gxv;
        __syncthreads();

        // ---- mma: acc[mt][nt] over warp's 4 k-tiles, 3 split terms ----
        float acc[4][2][4];
#pragma unroll
        for (int mt = 0; mt < 4; mt++)
#pragma unroll
            for (int nt = 0; nt < 2; nt++)
#pragma unroll
                for (int q = 0; q < 4; q++) acc[mt][nt][q] = 0.f;

        {
            uint32_t ca = w * 128 + (lane >> 4) * 16;
            int arw = (lane & 15);
#pragma unroll
            for (int kt = 0; kt < 4; kt++) {
#pragma unroll
                for (int mt = 0; mt < 4; mt++) {
                    uint32_t aoff = (mt * 16 + arw) * 1040 + ca + kt * 32;
                    uint32_t Ah[4], Al[4];
                    ldsm4(Ah, sbase + SM_HH + aoff);
                    ldsm4(Al, sbase + SM_HL + aoff);
#pragma unroll
                    for (int nt = 0; nt < 2; nt++) {
                        mma16816(acc[mt][nt], Ah, Bh[nt][kt][0], Bh[nt][kt][1]);
                        mma16816(acc[mt][nt], Ah, Bl[nt][kt][0], Bl[nt][kt][1]);
                        mma16816(acc[mt][nt], Al, Bh[nt][kt][0], Bh[nt][kt][1]);
                    }
                }
            }
        }

        // ---- store partials: P[w][b][n], row stride 24 floats ----
        {
            int g = lane >> 2, tg = lane & 3;
            uint32_t base = SM_P + w * 6144 + tg * 8;
#pragma unroll
            for (int mt = 0; mt < 4; mt++)
#pragma unroll
                for (int nt = 0; nt < 2; nt++) {
                    *(float2*)(smp + base + (mt * 16 + g) * 96 + nt * 32) =
                        make_float2(acc[mt][nt][0], acc[mt][nt][1]);
                    *(float2*)(smp + base + (mt * 16 + g + 8) * 96 + nt * 32) =
                        make_float2(acc[mt][nt][2], acc[mt][nt][3]);
                }
        }
        __syncthreads();

        // ---- reduce over 8 warps: thread (b, jq) gets 4 gates as float4 ----
        float4 G = make_float4(0.f, 0.f, 0.f, 0.f);
#pragma unroll
        for (int ww = 0; ww < 8; ww++) {
            float4 p = *(const float4*)(smp + SM_P + ww * 6144 + b * 96 + jq * 16);
            G.x += p.x; G.y += p.y; G.z += p.z; G.w += p.w;
        }

        float xi = G.x + gxs[b * 16 + 0  + jq * 0 + jq + 0 * 4];  // placeholder avoided below
        // correct indexing: gxs[b*16 + gate*4 + jq]
        xi       = G.x + gxs[b * 16 + 0 * 4 + jq];
        float xf = G.y + gxs[b * 16 + 1 * 4 + jq];
        float xg = G.z + gxs[b * 16 + 2 * 4 + jq];
        float xo = G.w + gxs[b * 16 + 3 * 4 + jq];
        float si = 1.f / (1.f + expf(-xi));
        float sf = 1.f / (1.f + expf(-xf));
        float tg2 = tanhf(xg);
        float so = 1.f / (1.f + expf(-xo));
        c = sf * c + si * tg2;
        h = so * tanhf(c);

        out[((size_t)b * TT + t) * HH + j] = h;
        __nv_bfloat16 hhi = __float2bfloat16(h);
        __nv_bfloat16 hlo = __float2bfloat16(h - __bfloat162float(hhi));
        int nb = (t & 1) ^ 1;
        g_hh[nb][b * HH + j] = hhi;
        g_hl[nb][b * HH + j] = hlo;

        // ---- grid barrier ----
        __threadfence();
        __syncthreads();
        if (tid == 0) {
            atomicAdd(&g_bar, 1u);
            while (*(volatile unsigned*)&g_bar < target) { }
            __threadfence();
        }
        __syncthreads();
        target += NC;
    }

    out[(size_t)BB * TT * HH + (size_t)b * HH + j] = h;
    out[(size_t)BB * TT * HH + BB * HH + (size_t)b * HH + j] = c;
}

extern "C" void kernel_launch(void* const* d_in, const int* in_sizes, int n_in,
                              void* d_out, int out_size)
{
    const float* x  = (const float*)d_in[0];
    const float* Wx = (const float*)d_in[1];
    const float* bx = (const float*)d_in[2];
    const float* Wh = (const float*)d_in[3];
    const float* bh = (const float*)d_in[4];
    float* out = (float*)d_out;

    init_k<<<32, 256>>>();
    cvt_x_kernel<<<2048, 256>>>(x);
    cvt_w_kernel<<<64, 256>>>(Wx);
    cvt_wh_kernel<<<64, 256>>>(Wh);

    cudaFuncSetAttribute(gemm_x_mma,
                         cudaFuncAttributeMaxDynamicSharedMemorySize, GSMEM_TOTAL);
    dim3 grid_g(GG / 128, 131072 / 128);
    gemm_x_mma<<<grid_g, 256, GSMEM_TOTAL>>>(bx, bh);

    cudaFuncSetAttribute(lstm_rec_kernel,
                         cudaFuncAttributeMaxDynamicSharedMemorySize, RSMEM_TOTAL);
    lstm_rec_kernel<<<NC, TPB, RSMEM_TOTAL>>>(out);
    (void)in_sizes; (void)n_in; (void)out_size;
}

// round 9
// speedup vs baseline: 3.0241x; 1.3477x over previous
#include <cuda_runtime.h>
#include <cuda_bf16.h>
#include <math.h>
#include <stdint.h>

#define BB 64
#define TT 2048
#define II 512
#define HH 512
#define GG 2048
#define NC 128
#define TPB 256

__device__ float         g_gatesx[(size_t)BB * TT * GG];
__device__ __nv_bfloat16 g_xh[(size_t)BB * TT * II];
__device__ __nv_bfloat16 g_xl[(size_t)BB * TT * II];
__device__ __nv_bfloat16 g_wxh[(size_t)GG * II];
__device__ __nv_bfloat16 g_wxl[(size_t)GG * II];
__device__ __nv_bfloat16 g_whh[(size_t)GG * HH];
__device__ __nv_bfloat16 g_whl[(size_t)GG * HH];
__device__ __nv_bfloat16 g_hTh[2][HH * BB];   // h hi, transposed [j][b]
__device__ __nv_bfloat16 g_hTl[2][HH * BB];   // h lo, transposed
__device__ unsigned      g_bar;

__device__ __forceinline__ uint32_t smem_u32(const void* p) {
    return (uint32_t)__cvta_generic_to_shared(p);
}
#define SWZ(o) ((o) ^ (((o) >> 3) & 0x70))

__device__ __forceinline__ void ldsm4(uint32_t* r, uint32_t a) {
    asm volatile("ldmatrix.sync.aligned.m8n8.x4.shared.b16 {%0,%1,%2,%3}, [%4];"
                 : "=r"(r[0]), "=r"(r[1]), "=r"(r[2]), "=r"(r[3]) : "r"(a));
}
__device__ __forceinline__ void ldsm4t(uint32_t* r, uint32_t a) {
    asm volatile("ldmatrix.sync.aligned.m8n8.x4.trans.shared.b16 {%0,%1,%2,%3}, [%4];"
                 : "=r"(r[0]), "=r"(r[1]), "=r"(r[2]), "=r"(r[3]) : "r"(a));
}
__device__ __forceinline__ void mma16816(float* c, const uint32_t* a,
                                         uint32_t b0, uint32_t b1) {
    asm volatile(
        "mma.sync.aligned.m16n8k16.row.col.f32.bf16.bf16.f32 "
        "{%0,%1,%2,%3},{%4,%5,%6,%7},{%8,%9},{%0,%1,%2,%3};"
        : "+f"(c[0]), "+f"(c[1]), "+f"(c[2]), "+f"(c[3])
        : "r"(a[0]), "r"(a[1]), "r"(a[2]), "r"(a[3]), "r"(b0), "r"(b1));
}
__device__ __forceinline__ void cpasync16(uint32_t s, const void* g) {
    asm volatile("cp.async.cg.shared.global [%0], [%1], 16;" :: "r"(s), "l"(g));
}
#define CP_COMMIT() asm volatile("cp.async.commit_group;" ::: "memory")
#define CP_WAIT(N)  asm volatile("cp.async.wait_group %0;" :: "n"(N) : "memory")

__device__ __forceinline__ void bar_arrive() {
    asm volatile("red.release.gpu.global.add.u32 [%0], %1;"
                 :: "l"(&g_bar), "r"(1u) : "memory");
}
__device__ __forceinline__ unsigned bar_read() {
    unsigned v;
    asm volatile("ld.acquire.gpu.global.u32 %0, [%1];" : "=r"(v) : "l"(&g_bar)
                 : "memory");
    return v;
}

__global__ void init_k() {
    int i = blockIdx.x * blockDim.x + threadIdx.x;
    if (i == 0) g_bar = 0u;
    for (int k = i; k < BB * HH; k += gridDim.x * blockDim.x) {
        g_hTh[0][k] = __float2bfloat16(0.f);
        g_hTl[0][k] = __float2bfloat16(0.f);
    }
}

// ---- fp32 -> bf16 hi/lo split ----
__device__ __forceinline__ void split4(float4 v, __nv_bfloat16* hi, __nv_bfloat16* lo,
                                       size_t i) {
    __nv_bfloat16 hx = __float2bfloat16(v.x), hy = __float2bfloat16(v.y);
    __nv_bfloat16 hz = __float2bfloat16(v.z), hw = __float2bfloat16(v.w);
    ((__nv_bfloat162*)hi)[2 * i]     = __halves2bfloat162(hx, hy);
    ((__nv_bfloat162*)hi)[2 * i + 1] = __halves2bfloat162(hz, hw);
    ((__nv_bfloat162*)lo)[2 * i] = __halves2bfloat162(
        __float2bfloat16(v.x - __bfloat162float(hx)),
        __float2bfloat16(v.y - __bfloat162float(hy)));
    ((__nv_bfloat162*)lo)[2 * i + 1] = __halves2bfloat162(
        __float2bfloat16(v.z - __bfloat162float(hz)),
        __float2bfloat16(v.w - __bfloat162float(hw)));
}
__global__ void cvt_x_kernel(const float* __restrict__ src) {
    size_t n4 = (size_t)BB * TT * II / 4, st = (size_t)gridDim.x * blockDim.x;
    for (size_t i = blockIdx.x * (size_t)blockDim.x + threadIdx.x; i < n4; i += st)
        split4(((const float4*)src)[i], g_xh, g_xl, i);
}
__global__ void cvt_w_kernel(const float* __restrict__ src) {
    size_t n4 = (size_t)GG * II / 4, st = (size_t)gridDim.x * blockDim.x;
    for (size_t i = blockIdx.x * (size_t)blockDim.x + threadIdx.x; i < n4; i += st)
        split4(((const float4*)src)[i], g_wxh, g_wxl, i);
}
__global__ void cvt_wh_kernel(const float* __restrict__ src) {
    size_t n4 = (size_t)GG * HH / 4, st = (size_t)gridDim.x * blockDim.x;
    for (size_t i = blockIdx.x * (size_t)blockDim.x + threadIdx.x; i < n4; i += st)
        split4(((const float4*)src)[i], g_whh, g_whl, i);
}

// ---- phase 1: mma.sync split-bf16 GEMM (validated in R6/R7) ----
#define STAGE_BYTES 65536
#define GSMEM_TOTAL (1024 + 2 * STAGE_BYTES)

__global__ __launch_bounds__(256) void gemm_x_mma(
    const float* __restrict__ bx, const float* __restrict__ bh)
{
    extern __shared__ char smem[];
    float* bias_s = (float*)smem;
    char*  tiles  = smem + 1024;
    const uint32_t tb = smem_u32(tiles);
    const int tid = threadIdx.x, lane = tid & 31, w = tid >> 5;
    const int wm = w & 3, wn = w >> 2;
    const int n0 = blockIdx.x * 128;
    const size_t m0 = (size_t)blockIdx.y * 128;

    if (tid < 128) bias_s[tid] = bx[n0 + tid] + bh[n0 + tid];

    auto stage = [&](int c, int buf) {
        uint32_t base = tb + buf * STAGE_BYTES;
#pragma unroll
        for (int i = 0; i < 16; i++) {
            int idx = tid + i * 256;
            int t = idx >> 10, r = (idx >> 3) & 127, ck = idx & 7;
            const __nv_bfloat16* src;
            if (t == 0)      src = g_xh  + (m0 + r) * II;
            else if (t == 1) src = g_xl  + (m0 + r) * II;
            else if (t == 2) src = g_wxh + (size_t)(n0 + r) * II;
            else             src = g_wxl + (size_t)(n0 + r) * II;
            cpasync16(base + t * 16384 + SWZ(r * 128 + ck * 16),
                      (const char*)src + c * 128 + ck * 16);
        }
        CP_COMMIT();
    };

    float acc[2][8][4];
#pragma unroll
    for (int a = 0; a < 2; a++)
#pragma unroll
        for (int bq = 0; bq < 8; bq++)
#pragma unroll
            for (int q = 0; q < 4; q++) acc[a][bq][q] = 0.f;

    stage(0, 0);
    for (int c = 0; c < 8; c++) {
        CP_WAIT(0);
        __syncthreads();
        if (c < 7) stage(c + 1, (c + 1) & 1);

        const uint32_t bA = tb + (c & 1) * STAGE_BYTES;
#pragma unroll
        for (int kk = 0; kk < 4; kk++) {
            const int kb = kk * 32;
            uint32_t ah[2][4], al[2][4];
#pragma unroll
            for (int mt = 0; mt < 2; mt++) {
                int arow = wm * 32 + mt * 16 + (lane & 15);
                uint32_t aoff = SWZ(arow * 128 + kb + (lane >> 4) * 16);
                ldsm4(ah[mt], bA + aoff);
                ldsm4(al[mt], bA + 16384 + aoff);
            }
#pragma unroll
            for (int ng = 0; ng < 4; ng++) {
                int brow = wn * 64 + ng * 16 + ((lane >> 4) & 1) * 8 + (lane & 7);
                uint32_t boff = SWZ(brow * 128 + kb + ((lane >> 3) & 1) * 16);
                uint32_t bhf[4], blf[4];
                ldsm4(bhf, bA + 32768 + boff);
                ldsm4(blf, bA + 49152 + boff);
#pragma unroll
                for (int mt = 0; mt < 2; mt++) {
                    mma16816(acc[mt][ng * 2],     ah[mt], bhf[0], bhf[1]);
                    mma16816(acc[mt][ng * 2],     ah[mt], blf[0], blf[1]);
                    mma16816(acc[mt][ng * 2],     al[mt], bhf[0], bhf[1]);
                    mma16816(acc[mt][ng * 2 + 1], ah[mt], bhf[2], bhf[3]);
                    mma16816(acc[mt][ng * 2 + 1], ah[mt], blf[2], blf[3]);
                    mma16816(acc[mt][ng * 2 + 1], al[mt], bhf[2], bhf[3]);
                }
            }
        }
        __syncthreads();
    }

#pragma unroll
    for (int mt = 0; mt < 2; mt++) {
        size_t row = m0 + wm * 32 + mt * 16 + (lane >> 2);
#pragma unroll
        for (int nf = 0; nf < 8; nf++) {
            int cl = wn * 64 + nf * 8 + (lane & 3) * 2;
            float b0 = bias_s[cl], b1 = bias_s[cl + 1];
            float* p0 = g_gatesx + row * GG + n0 + cl;
            float* p1 = g_gatesx + (row + 8) * GG + n0 + cl;
            *(float2*)p0 = make_float2(acc[mt][nf][0] + b0, acc[mt][nf][1] + b1);
            *(float2*)p1 = make_float2(acc[mt][nf][2] + b0, acc[mt][nf][3] + b1);
        }
    }
}

// ---- phase 2: persistent recurrence ----
// Warp-local cp.async staging of transposed h (contiguous 8KB/warp slice),
// pipelined per kt against mma.sync; release/acquire grid barrier (no L1 flush).
#define SM_HH  0                  // 8 warp tiles x 8KB (h hi, swizzled)
#define SM_HL  65536              // h lo
#define SM_P   131072             // partials: 8w x 64b x 80B = 40960
#define SM_GX  172032             // gates_x tile: 4096
#define SM_HST 176128             // h restage: hi 512B + lo 512B
#define SM_OST 177152             // out restage: 64 x float4 = 1024
#define RSMEM_TOTAL 178176

__global__ __launch_bounds__(256) void lstm_rec_kernel(float* __restrict__ out)
{
    extern __shared__ char smp[];
    const uint32_t sbase = smem_u32(smp);
    const int tid = threadIdx.x, lane = tid & 31, w = tid >> 5;
    const int j0 = blockIdx.x * 4;
    const int b  = tid & 63;
    const int jq = tid >> 6;
    const int j  = j0 + jq;
    float* gxs = (float*)(smp + SM_GX);

    // ---- stage Wh slice (16 rows x 512, hi+lo) into scratch (stride 1040) ----
#pragma unroll
    for (int i = 0; i < 4; i++) {
        int idx = tid + i * 256;
        int n = idx >> 6, cc = idx & 63;
        int gate = n & 3, q = n >> 2;
        size_t grow = (size_t)(gate * HH + j0 + q) * HH;
        *(uint4*)(smp + SM_HH + n * 1040 + cc * 16) =
            *((const uint4*)(g_whh + grow) + cc);
        *(uint4*)(smp + SM_HH + 16640 + n * 1040 + cc * 16) =
            *((const uint4*)(g_whl + grow) + cc);
    }
    __syncthreads();

    // ---- B-frags once: warp w owns k in [w*64, (w+1)*64) ----
    uint32_t Bh[2][4][2], Bl[2][4][2];
    {
        int brow = ((lane >> 4) & 1) * 8 + (lane & 7);
        uint32_t cb = w * 128 + ((lane >> 3) & 1) * 16;
#pragma unroll
        for (int kt = 0; kt < 4; kt++) {
            uint32_t off = brow * 1040 + cb + kt * 32;
            uint32_t r[4];
            ldsm4(r, sbase + SM_HH + off);
            Bh[0][kt][0] = r[0]; Bh[0][kt][1] = r[1];
            Bh[1][kt][0] = r[2]; Bh[1][kt][1] = r[3];
            ldsm4(r, sbase + SM_HH + 16640 + off);
            Bl[0][kt][0] = r[0]; Bl[0][kt][1] = r[1];
            Bl[1][kt][0] = r[2]; Bl[1][kt][1] = r[3];
        }
    }
    __syncthreads();   // scratch region free

    const int sb = tid >> 2, sg = tid & 3;
    float c = 0.f, h = 0.f;
    unsigned target = NC;

    for (int t = 0; t < TT; t++) {
        // gates_x prefetch (independent of h)
        float4 gxv = *(const float4*)(g_gatesx +
                        ((size_t)sb * TT + t) * GG + (size_t)sg * HH + j0);

        // ---- warp-local cp.async: contiguous 8KB hi + 8KB lo slice of hT ----
        {
            const char* srch = (const char*)g_hTh[t & 1] + (size_t)w * 8192;
            const char* srcl = (const char*)g_hTl[t & 1] + (size_t)w * 8192;
#pragma unroll
            for (int kt = 0; kt < 4; kt++) {
#pragma unroll
                for (int q = 0; q < 4; q++) {
                    int idx = q * 32 + lane;              // 0..127
                    int r = kt * 16 + (idx >> 3), ck = idx & 7;
                    uint32_t d = SWZ(r * 128 + ck * 16);
                    cpasync16(sbase + SM_HH + w * 8192 + d, srch + r * 128 + ck * 16);
                    cpasync16(sbase + SM_HL + w * 8192 + d, srcl + r * 128 + ck * 16);
                }
                CP_COMMIT();
            }
        }
        ((float4*)gxs)[tid] = gxv;

        // ---- MMA, pipelined per kt ----
        float acc[4][2][4];
#pragma unroll
        for (int mt = 0; mt < 4; mt++)
#pragma unroll
            for (int nt = 0; nt < 2; nt++)
#pragma unroll
                for (int q = 0; q < 4; q++) acc[mt][nt][q] = 0.f;

        const int khalf = lane >> 4, mhalf = (lane >> 3) & 1, krow = lane & 7;
#define REC_KT(KT, WN)                                                         \
        {                                                                      \
            CP_WAIT(WN);                                                       \
            _Pragma("unroll")                                                  \
            for (int mt = 0; mt < 4; mt++) {                                   \
                uint32_t aoff = SWZ((KT * 16 + khalf * 8 + krow) * 128 +       \
                                    mt * 32 + mhalf * 16);                     \
                uint32_t Ah[4], Al[4];                                         \
                ldsm4t(Ah, sbase + SM_HH + w * 8192 + aoff);                   \
                ldsm4t(Al, sbase + SM_HL + w * 8192 + aoff);                   \
                _Pragma("unroll")                                              \
                for (int nt = 0; nt < 2; nt++) {                               \
                    mma16816(acc[mt][nt], Ah, Bh[nt][KT][0], Bh[nt][KT][1]);   \
                    mma16816(acc[mt][nt], Ah, Bl[nt][KT][0], Bl[nt][KT][1]);   \
                    mma16816(acc[mt][nt], Al, Bh[nt][KT][0], Bh[nt][KT][1]);   \
                }                                                              \
            }                                                                  \
        }
        REC_KT(0, 3) REC_KT(1, 2) REC_KT(2, 1) REC_KT(3, 0)
#undef REC_KT

        // ---- partial store: [w][brow][n], row stride 80B ----
        {
            int g = lane >> 2, tg = lane & 3;
            uint32_t base = SM_P + w * 5120 + tg * 8;
#pragma unroll
            for (int mt = 0; mt < 4; mt++)
#pragma unroll
                for (int nt = 0; nt < 2; nt++) {
                    *(float2*)(smp + base + (mt * 16 + g) * 80 + nt * 32) =
                        make_float2(acc[mt][nt][0], acc[mt][nt][1]);
                    *(float2*)(smp + base + (mt * 16 + g + 8) * 80 + nt * 32) =
                        make_float2(acc[mt][nt][2], acc[mt][nt][3]);
                }
        }
        __syncthreads();

        // ---- reduce over warps + pointwise cell ----
        float4 G = make_float4(0.f, 0.f, 0.f, 0.f);
#pragma unroll
        for (int ww = 0; ww < 8; ww++) {
            float4 p = *(const float4*)(smp + SM_P + ww * 5120 + b * 80 + jq * 16);
            G.x += p.x; G.y += p.y; G.z += p.z; G.w += p.w;
        }
        float xi = G.x + gxs[b * 16 + 0 * 4 + jq];
        float xf = G.y + gxs[b * 16 + 1 * 4 + jq];
        float xg = G.z + gxs[b * 16 + 2 * 4 + jq];
        float xo = G.w + gxs[b * 16 + 3 * 4 + jq];
        float si = __fdividef(1.f, 1.f + __expf(-xi));
        float sf = __fdividef(1.f, 1.f + __expf(-xf));
        float tg2 = tanhf(xg);
        float so = __fdividef(1.f, 1.f + __expf(-xo));
        c = sf * c + si * tg2;
        h = so * tanhf(c);

        __nv_bfloat16 hhi = __float2bfloat16(h);
        __nv_bfloat16 hlo = __float2bfloat16(h - __bfloat162float(hhi));
        ((__nv_bfloat16*)(smp + SM_HST))[jq * 64 + b] = hhi;
        ((__nv_bfloat16*)(smp + SM_HST + 512))[jq * 64 + b] = hlo;
        ((float*)(smp + SM_OST))[b * 4 + jq] = h;
        __syncthreads();

        // ---- coalesced hT exchange write (must precede arrive) ----
        int nb = (t & 1) ^ 1;
        if (tid < 32) {
            int row = tid >> 3, ck = tid & 7;
            uint4 v = *(const uint4*)(smp + SM_HST + row * 128 + ck * 16);
            ((uint4*)((char*)g_hTh[nb] + (size_t)(j0 + row) * 128))[ck] = v;
        } else if (tid < 64) {
            int td = tid - 32, row = td >> 3, ck = td & 7;
            uint4 v = *(const uint4*)(smp + SM_HST + 512 + row * 128 + ck * 16);
            ((uint4*)((char*)g_hTl[nb] + (size_t)(j0 + row) * 128))[ck] = v;
        }
        __syncthreads();

        if (tid == 0) bar_arrive();

        // coalesced out writes overlap the spin (not consumed cross-CTA)
        if (tid >= 64 && tid < 128) {
            int bb2 = tid - 64;
            float4 v = *(const float4*)(smp + SM_OST + bb2 * 16);
            *(float4*)(out + ((size_t)bb2 * TT + t) * HH + j0) = v;
        }

        if (lane == 0) { while (bar_read() < target) { } }
        __syncwarp();
        target += NC;
    }

    out[(size_t)BB * TT * HH + (size_t)b * HH + j] = h;
    out[(size_t)BB * TT * HH + BB * HH + (size_t)b * HH + j] = c;
}

extern "C" void kernel_launch(void* const* d_in, const int* in_sizes, int n_in,
                              void* d_out, int out_size)
{
    const float* x  = (const float*)d_in[0];
    const float* Wx = (const float*)d_in[1];
    const float* bx = (const float*)d_in[2];
    const float* Wh = (const float*)d_in[3];
    const float* bh = (const float*)d_in[4];
    float* out = (float*)d_out;

    init_k<<<32, 256>>>();
    cvt_x_kernel<<<2048, 256>>>(x);
    cvt_w_kernel<<<64, 256>>>(Wx);
    cvt_wh_kernel<<<64, 256>>>(Wh);

    cudaFuncSetAttribute(gemm_x_mma,
                         cudaFuncAttributeMaxDynamicSharedMemorySize, GSMEM_TOTAL);
    dim3 grid_g(GG / 128, 131072 / 128);
    gemm_x_mma<<<grid_g, 256, GSMEM_TOTAL>>>(bx, bh);

    cudaFuncSetAttribute(lstm_rec_kernel,
                         cudaFuncAttributeMaxDynamicSharedMemorySize, RSMEM_TOTAL);
    lstm_rec_kernel<<<NC, TPB, RSMEM_TOTAL>>>(out);
    (void)in_sizes; (void)n_in; (void)out_size;
}